// round 13
// baseline (speedup 1.0000x reference)
#include <cuda_runtime.h>
#include <cuda_fp16.h>
#include <cstdint>

#define BB 32768
#define II 256
#define HH 512
#define KK 768        // I + H, single fp16 pass
#define NN 2048       // 4 * H gates

__device__ __half g_A[(size_t)BB * KK];   // [B][K]  fp16
__device__ __half g_W[(size_t)NN * KK];   // [N][K]  fp16, N interleaved (u,g)
__device__ float g_bias[NN];

// ---------------------------------------------------------------------------
// PTX helpers
// ---------------------------------------------------------------------------
__device__ __forceinline__ void cp_async16(uint32_t saddr, const void* gaddr) {
    asm volatile("cp.async.cg.shared.global [%0], [%1], 16;\n"
                 :: "r"(saddr), "l"(gaddr));
}
__device__ __forceinline__ void ldsm_x4(uint32_t* r, uint32_t addr) {
    asm volatile("ldmatrix.sync.aligned.m8n8.x4.shared.b16 {%0,%1,%2,%3}, [%4];\n"
                 : "=r"(r[0]), "=r"(r[1]), "=r"(r[2]), "=r"(r[3]) : "r"(addr));
}
__device__ __forceinline__ void mma16816(float* d, const uint32_t* a, const uint32_t* b) {
    asm volatile(
        "mma.sync.aligned.m16n8k16.row.col.f32.f16.f16.f32 "
        "{%0,%1,%2,%3}, {%4,%5,%6,%7}, {%8,%9}, {%0,%1,%2,%3};\n"
        : "+f"(d[0]), "+f"(d[1]), "+f"(d[2]), "+f"(d[3])
        : "r"(a[0]), "r"(a[1]), "r"(a[2]), "r"(a[3]), "r"(b[0]), "r"(b[1]));
}

// ---------------------------------------------------------------------------
// Merged prep kernel (fp16 A, W, bias). Gate cols interleaved:
// out col n <-> (u=n>>2, g=n&3); src row = g*H+u.
// ---------------------------------------------------------------------------
#define NB_A (BB * (KK / 4) / 256)     // 24576
#define NB_W (NN * (KK / 4) / 256)     // 1536

__global__ void prep_all(const float* __restrict__ x, const float* __restrict__ h,
                         const float* __restrict__ Wx, const float* __restrict__ bx,
                         const float* __restrict__ Wh, const float* __restrict__ bh) {
    int bidx = blockIdx.x;
    if (bidx < NB_A) {
        int idx = bidx * 256 + threadIdx.x;
        int b = idx / (KK / 4), kc = idx % (KK / 4);
        int k0 = kc * 4;
        float4 v;
        if (k0 < II) v = *(const float4*)(x + (size_t)b * II + k0);
        else         v = *(const float4*)(h + (size_t)b * HH + (k0 - II));
        union { __half h[4]; uint2 u2; } p;
        p.h[0] = __float2half_rn(v.x); p.h[1] = __float2half_rn(v.y);
        p.h[2] = __float2half_rn(v.z); p.h[3] = __float2half_rn(v.w);
        *(uint2*)(g_A + (size_t)b * KK + k0) = p.u2;
    } else {
        int idx = (bidx - NB_A) * 256 + threadIdx.x;
        int n = idx / (KK / 4), kc = idx % (KK / 4);
        int u = n >> 2, g = n & 3, src = g * HH + u;
        int k0 = kc * 4;
        float4 v;
        if (k0 < II) v = *(const float4*)(Wx + (size_t)src * II + k0);
        else         v = *(const float4*)(Wh + (size_t)src * HH + (k0 - II));
        union { __half h[4]; uint2 u2; } p;
        p.h[0] = __float2half_rn(v.x); p.h[1] = __float2half_rn(v.y);
        p.h[2] = __float2half_rn(v.z); p.h[3] = __float2half_rn(v.w);
        *(uint2*)(g_W + (size_t)n * KK + k0) = p.u2;
        if (kc == 0) g_bias[n] = bx[src] + bh[src];
    }
}

// ---------------------------------------------------------------------------
// Fused GEMM + LSTM epilogue — HIGH-OCCUPANCY VARIANT.
// CTA tile 128x128, 512 threads, 16 warps in 4(M)x4(N) grid; warp tile 32x32.
// acc = 32 regs/thread -> fits 64-reg cap -> 2 CTAs/SM = 32 warps/SM.
// K chunk 96, 2-stage ring. Stage: 3 blocks of [128 rows x 64B]/operand,
// swizzle c ^= (row>>1)&3. c_in tile prefetched. Single-phase epilogue.
// ---------------------------------------------------------------------------
#define KCH 96
#define NK  (KK / KCH)        // 8
#define BLKB 8192             // one 128x64B block
#define TILEB (3 * BLKB)      // 24576 per operand per stage
#define STG  (2 * TILEB)      // 49152 per stage (A + B)
#define NSTAGE 2
#define C_OFF (NSTAGE * STG)  // 98304
#define SMEM_DYN (C_OFF + 16384)  // 114688

#define SWZ(row, c) ((((c) ^ (((row) >> 1) & 3)) << 4))

__global__ void __launch_bounds__(512, 2)
lstm_gemm(const float* __restrict__ c_in, float* __restrict__ out) {
    extern __shared__ __align__(16) unsigned char smem[];
    __shared__ float bias_s[128];

    const int tid  = threadIdx.x;
    const int warp = tid >> 5, lane = tid & 31;
    const int wm = warp >> 2, wn = warp & 3;       // 4x4 warp grid
    const int mBase = blockIdx.y * 128;
    const int nBase = blockIdx.x * 128;

    const uint32_t sbase = (uint32_t)__cvta_generic_to_shared(smem);
    if (tid < 128) bias_s[tid] = g_bias[nBase + tid];

    float acc[2][4][4];
#pragma unroll
    for (int mi = 0; mi < 2; mi++)
#pragma unroll
        for (int ni = 0; ni < 4; ni++)
#pragma unroll
            for (int d = 0; d < 4; d++) acc[mi][ni][d] = 0.f;

    const __half* gAp = g_A + (size_t)mBase * KK;
    const __half* gWp = g_W + (size_t)nBase * KK;

    // Precomputed per-thread ldsm base offsets (kk toggles bit 5 via XOR,
    // blk adds BLKB — both carry-free against these bases).
    uint32_t a_base[2], b_base[2];
#pragma unroll
    for (int mi = 0; mi < 2; mi++) {
        int row = wm * 32 + mi * 16 + (lane & 15);
        a_base[mi] = row * 64 + (((lane >> 4) ^ ((row >> 1) & 3)) << 4);
    }
#pragma unroll
    for (int p = 0; p < 2; p++) {
        int nrow = wn * 32 + p * 16 + ((lane >> 4) << 3) + (lane & 7);
        b_base[p] = TILEB + nrow * 64 + ((((lane >> 3) & 1) ^ ((nrow >> 1) & 3)) << 4);
    }

    // 3072 16B-chunks per stage (A: j 0-2, B: j 3-5), 6 per thread.
    auto load_stage = [&](int kt, int stage) {
        uint32_t so = sbase + stage * STG;
#pragma unroll
        for (int j = 0; j < 6; j++) {
            int idx = tid + j * 512;
            int isB = (j >= 3);
            int rem = idx - isB * 1536;
            int blk = rem >> 9;
            int row = (rem >> 2) & 127;
            int c   = rem & 3;
            const __half* src = (isB ? gWp : gAp)
                              + (size_t)row * KK + kt * KCH + blk * 32 + c * 8;
            cp_async16(so + isB * TILEB + blk * BLKB + row * 64 + SWZ(row, c), src);
        }
    };

    // Prefetch c_in tile: 128 rows x 32 f32 = 16KB (1024 chunks, 2/thread).
#pragma unroll
    for (int j = 0; j < 2; j++) {
        int idx = tid + j * 512;
        int row = idx >> 3, ch = idx & 7;
        cp_async16(sbase + C_OFF + row * 128 + ch * 16,
                   c_in + (size_t)(mBase + row) * HH + (nBase >> 2) + ch * 4);
    }
    load_stage(0, 0);
    asm volatile("cp.async.commit_group;\n");

    int koff = warp % 6;           // stagger k16-step start across warps

    for (int kt = 0; kt < NK; kt++) {
        asm volatile("cp.async.wait_group 0;\n");
        __syncthreads();           // all warps done with the other stage

        const uint32_t so = sbase + (kt & 1) * STG;
#pragma unroll
        for (int ksi = 0; ksi < 6; ksi++) {        // six k16 steps per chunk
            int ks = ksi + koff; if (ks >= 6) ks -= 6;
            const int blk = ks >> 1, kk = ks & 1;
            const uint32_t sb = so + blk * BLKB;
            const uint32_t kx = kk << 5;
            uint32_t a_regs[2][4];
#pragma unroll
            for (int mi = 0; mi < 2; mi++)
                ldsm_x4(a_regs[mi], (sb + a_base[mi]) ^ kx);
#pragma unroll
            for (int p = 0; p < 2; p++) {          // each x4 covers two n-tiles
                uint32_t r[4];
                ldsm_x4(r, (sb + b_base[p]) ^ kx);
#pragma unroll
                for (int mi = 0; mi < 2; mi++) {
                    mma16816(acc[mi][2 * p],     a_regs[mi], r);
                    mma16816(acc[mi][2 * p + 1], a_regs[mi], r + 2);
                }
            }

            // Refill the other stage after the first k16 step: safe because
            // this iteration's barrier proved all warps finished consuming it.
            if (ksi == 0 && kt + 1 < NK) {
                load_stage(kt + 1, (kt + 1) & 1);
                asm volatile("cp.async.commit_group;\n");
            }
        }
    }

    // ---- Fused LSTM epilogue (single phase through smem) ----
    float* egs = (float*)smem;                      // [128][130] = 66560 B
    const float* c_s = (const float*)(smem + C_OFF);
    __syncthreads();
#pragma unroll
    for (int mi = 0; mi < 2; mi++)
#pragma unroll
        for (int ni = 0; ni < 4; ni++) {
            int r = wm * 32 + mi * 16 + (lane >> 2);
            int col = wn * 32 + ni * 8 + ((lane & 3) << 1);
            egs[r * 130 + col]           = acc[mi][ni][0];
            egs[r * 130 + col + 1]       = acc[mi][ni][1];
            egs[(r + 8) * 130 + col]     = acc[mi][ni][2];
            egs[(r + 8) * 130 + col + 1] = acc[mi][ni][3];
        }
    __syncthreads();
#pragma unroll
    for (int i = 0; i < 8; i++) {
        int item = tid + i * 512;                   // 4096 (row, hidden) items
        int ml = item >> 5, u = item & 31;
        float gi = egs[ml * 130 + 4 * u]     + bias_s[4 * u];
        float gf = egs[ml * 130 + 4 * u + 1] + bias_s[4 * u + 1];
        float go = egs[ml * 130 + 4 * u + 2] + bias_s[4 * u + 2];
        float gc = egs[ml * 130 + 4 * u + 3] + bias_s[4 * u + 3];
        float it = 1.f / (1.f + __expf(-gi));
        float ft = 1.f / (1.f + __expf(-gf));
        float ot = 1.f / (1.f + __expf(-go));
        float tc = 1.f - 2.f / (1.f + __expf(2.f * gc));   // tanh via MUFU
        int mg = mBase + ml;
        int ug = (nBase >> 2) + u;
        float cv = c_s[ml * 32 + u];
        float ct = ft * cv + it * tc;
        float ht = ot * (1.f - 2.f / (1.f + __expf(2.f * ct)));
        out[(size_t)mg * HH + ug] = ct;
        out[(size_t)BB * HH + (size_t)mg * HH + ug] = ht;
    }
}

// ---------------------------------------------------------------------------
extern "C" void kernel_launch(void* const* d_in, const int* in_sizes, int n_in,
                              void* d_out, int out_size) {
    (void)in_sizes; (void)n_in; (void)out_size;
    const float* x  = (const float*)d_in[0];
    const float* h  = (const float*)d_in[1];
    const float* c  = (const float*)d_in[2];
    const float* Wx = (const float*)d_in[3];
    const float* bx = (const float*)d_in[4];
    const float* Wh = (const float*)d_in[5];
    const float* bh = (const float*)d_in[6];
    float* out = (float*)d_out;

    cudaFuncSetAttribute(lstm_gemm, cudaFuncAttributeMaxDynamicSharedMemorySize, SMEM_DYN);

    prep_all<<<NB_A + NB_W, 256>>>(x, h, Wx, bx, Wh, bh);
    lstm_gemm<<<dim3(NN / 128, BB / 128), 512, SMEM_DYN>>>(c, out);
}

// round 14
// speedup vs baseline: 1.0474x; 1.0474x over previous
#include <cuda_runtime.h>
#include <cuda_fp16.h>
#include <cstdint>

#define BB 32768
#define II 256
#define HH 512
#define KK 768        // I + H, single fp16 pass
#define NN 2048       // 4 * H gates

__device__ __half g_A[(size_t)BB * KK];   // [B][K]  fp16
__device__ __half g_W[(size_t)NN * KK];   // [N][K]  fp16, N interleaved (u,g)
__device__ float g_bias[NN];

// ---------------------------------------------------------------------------
// PTX helpers
// ---------------------------------------------------------------------------
__device__ __forceinline__ void cp_async16(uint32_t saddr, const void* gaddr) {
    asm volatile("cp.async.cg.shared.global [%0], [%1], 16;\n"
                 :: "r"(saddr), "l"(gaddr));
}
__device__ __forceinline__ void ldsm_x4(uint32_t* r, uint32_t addr) {
    asm volatile("ldmatrix.sync.aligned.m8n8.x4.shared.b16 {%0,%1,%2,%3}, [%4];\n"
                 : "=r"(r[0]), "=r"(r[1]), "=r"(r[2]), "=r"(r[3]) : "r"(addr));
}
__device__ __forceinline__ void mma16816(float* d, const uint32_t* a, const uint32_t* b) {
    asm volatile(
        "mma.sync.aligned.m16n8k16.row.col.f32.f16.f16.f32 "
        "{%0,%1,%2,%3}, {%4,%5,%6,%7}, {%8,%9}, {%0,%1,%2,%3};\n"
        : "+f"(d[0]), "+f"(d[1]), "+f"(d[2]), "+f"(d[3])
        : "r"(a[0]), "r"(a[1]), "r"(a[2]), "r"(a[3]), "r"(b[0]), "r"(b[1]));
}

// ---------------------------------------------------------------------------
// Merged prep kernel (fp16 A, W, bias). Gate cols interleaved:
// out col n <-> (u=n>>2, g=n&3); src row = g*H+u.
// ---------------------------------------------------------------------------
#define NB_A (BB * (KK / 4) / 256)     // 24576
#define NB_W (NN * (KK / 4) / 256)     // 1536

__global__ void prep_all(const float* __restrict__ x, const float* __restrict__ h,
                         const float* __restrict__ Wx, const float* __restrict__ bx,
                         const float* __restrict__ Wh, const float* __restrict__ bh) {
    int bidx = blockIdx.x;
    if (bidx < NB_A) {
        int idx = bidx * 256 + threadIdx.x;
        int b = idx / (KK / 4), kc = idx % (KK / 4);
        int k0 = kc * 4;
        float4 v;
        if (k0 < II) v = *(const float4*)(x + (size_t)b * II + k0);
        else         v = *(const float4*)(h + (size_t)b * HH + (k0 - II));
        union { __half h[4]; uint2 u2; } p;
        p.h[0] = __float2half_rn(v.x); p.h[1] = __float2half_rn(v.y);
        p.h[2] = __float2half_rn(v.z); p.h[3] = __float2half_rn(v.w);
        *(uint2*)(g_A + (size_t)b * KK + k0) = p.u2;
    } else {
        int idx = (bidx - NB_A) * 256 + threadIdx.x;
        int n = idx / (KK / 4), kc = idx % (KK / 4);
        int u = n >> 2, g = n & 3, src = g * HH + u;
        int k0 = kc * 4;
        float4 v;
        if (k0 < II) v = *(const float4*)(Wx + (size_t)src * II + k0);
        else         v = *(const float4*)(Wh + (size_t)src * HH + (k0 - II));
        union { __half h[4]; uint2 u2; } p;
        p.h[0] = __float2half_rn(v.x); p.h[1] = __float2half_rn(v.y);
        p.h[2] = __float2half_rn(v.z); p.h[3] = __float2half_rn(v.w);
        *(uint2*)(g_W + (size_t)n * KK + k0) = p.u2;
        if (kc == 0) g_bias[n] = bx[src] + bh[src];
    }
}

// ---------------------------------------------------------------------------
// Fused GEMM + LSTM epilogue (R12 config + interleaved inner pipeline).
// CTA tile 128x128, K chunk 96, 2-stage ring, 8 warps 4x2, warp tile 32x64.
// Stage: 3 blocks of [128 rows x 64B]/operand, swizzle c ^= (row>>1)&3.
// Inner loop: B-ldsm / mma-group interleave + A-fragment double buffer so
// LSU latency hides under tensor work (volatile-asm PTX order is load-bearing).
// 2 CTAs/SM. c_in tile prefetched at start.
// ---------------------------------------------------------------------------
#define KCH 96
#define NK  (KK / KCH)        // 8
#define BLKB 8192             // one 128x64B block
#define TILEB (3 * BLKB)      // 24576 per operand per stage
#define STG  (2 * TILEB)      // 49152 per stage (A + B)
#define NSTAGE 2
#define C_OFF (NSTAGE * STG)  // 98304
#define SMEM_DYN (C_OFF + 16384)  // 114688

#define SWZ(row, c) ((((c) ^ (((row) >> 1) & 3)) << 4))

__global__ void __launch_bounds__(256, 2)
lstm_gemm(const float* __restrict__ c_in, float* __restrict__ out) {
    extern __shared__ __align__(16) unsigned char smem[];
    __shared__ float bias_s[128];

    const int tid  = threadIdx.x;
    const int warp = tid >> 5, lane = tid & 31;
    const int wm = warp >> 1, wn = warp & 1;       // 4x2 warp grid
    const int mBase = blockIdx.y * 128;
    const int nBase = blockIdx.x * 128;

    const uint32_t sbase = (uint32_t)__cvta_generic_to_shared(smem);
    if (tid < 128) bias_s[tid] = g_bias[nBase + tid];

    float acc[2][8][4];
#pragma unroll
    for (int mi = 0; mi < 2; mi++)
#pragma unroll
        for (int ni = 0; ni < 8; ni++)
#pragma unroll
            for (int d = 0; d < 4; d++) acc[mi][ni][d] = 0.f;

    const __half* gAp = g_A + (size_t)mBase * KK;
    const __half* gWp = g_W + (size_t)nBase * KK;

    // Precomputed ldsm base offsets; kk toggles bit 5 via XOR (carry-free:
    // disjoint bit fields), blk adds BLKB.
    uint32_t a_base[2], b_base[4];
#pragma unroll
    for (int mi = 0; mi < 2; mi++) {
        int row = wm * 32 + mi * 16 + (lane & 15);
        a_base[mi] = row * 64 + (((lane >> 4) ^ ((row >> 1) & 3)) << 4);
    }
#pragma unroll
    for (int p = 0; p < 4; p++) {
        int nrow = wn * 64 + p * 16 + ((lane >> 4) << 3) + (lane & 7);
        b_base[p] = TILEB + nrow * 64
                  + ((((lane >> 3) & 1) ^ ((nrow >> 1) & 3)) << 4);
    }

    // 3072 16B-chunks per stage (A: j 0-5, B: j 6-11), 12 per thread.
    auto load_stage = [&](int kt, int stage) {
        uint32_t so = sbase + stage * STG;
#pragma unroll
        for (int j = 0; j < 12; j++) {
            int idx = tid + j * 256;
            int isB = (j >= 6);
            int rem = idx - isB * 1536;
            int blk = rem >> 9;
            int row = (rem >> 2) & 127;
            int c   = rem & 3;
            const __half* src = (isB ? gWp : gAp)
                              + (size_t)row * KK + kt * KCH + blk * 32 + c * 8;
            cp_async16(so + isB * TILEB + blk * BLKB + row * 64 + SWZ(row, c), src);
        }
    };

    // Prefetch c_in tile: 128 rows x 32 f32 = 16KB (1024 chunks, 4/thread).
#pragma unroll
    for (int j = 0; j < 4; j++) {
        int idx = tid + j * 256;
        int row = idx >> 3, ch = idx & 7;
        cp_async16(sbase + C_OFF + row * 128 + ch * 16,
                   c_in + (size_t)(mBase + row) * HH + (nBase >> 2) + ch * 4);
    }
    load_stage(0, 0);
    asm volatile("cp.async.commit_group;\n");

    const int koff = warp & 3;     // stagger k16-step start across SMSP warps

    for (int kt = 0; kt < NK; kt++) {
        asm volatile("cp.async.wait_group 0;\n");
        __syncthreads();           // all warps done with the other stage

        const uint32_t so = sbase + (kt & 1) * STG;
        int ks = koff;             // first k16 step for this warp
        uint32_t a_cur[2][4], a_nxt[2][4];
        {
            const uint32_t sb = so + (ks >> 1) * BLKB;
            const uint32_t kx = (uint32_t)(ks & 1) << 5;
            ldsm_x4(a_cur[0], (sb + a_base[0]) ^ kx);
            ldsm_x4(a_cur[1], (sb + a_base[1]) ^ kx);
        }
#pragma unroll
        for (int ksi = 0; ksi < 6; ksi++) {
            const uint32_t sb = so + (ks >> 1) * BLKB;
            const uint32_t kx = (uint32_t)(ks & 1) << 5;
            uint32_t b0[4], b1[4];
            // p0,p1 loads in flight while p0's mma group runs.
            ldsm_x4(b0, (sb + b_base[0]) ^ kx);
            ldsm_x4(b1, (sb + b_base[1]) ^ kx);
            mma16816(acc[0][0], a_cur[0], b0);
            mma16816(acc[0][1], a_cur[0], b0 + 2);
            mma16816(acc[1][0], a_cur[1], b0);
            mma16816(acc[1][1], a_cur[1], b0 + 2);
            ldsm_x4(b0, (sb + b_base[2]) ^ kx);      // p2 under p1's mma
            mma16816(acc[0][2], a_cur[0], b1);
            mma16816(acc[0][3], a_cur[0], b1 + 2);
            mma16816(acc[1][2], a_cur[1], b1);
            mma16816(acc[1][3], a_cur[1], b1 + 2);
            ldsm_x4(b1, (sb + b_base[3]) ^ kx);      // p3 under p2's mma
            int ksn = ks + 1; if (ksn == 6) ksn = 0;
            if (ksi < 5) {                           // next-step A under p2/p3 mma
                const uint32_t sbn = so + (ksn >> 1) * BLKB;
                const uint32_t kxn = (uint32_t)(ksn & 1) << 5;
                ldsm_x4(a_nxt[0], (sbn + a_base[0]) ^ kxn);
                ldsm_x4(a_nxt[1], (sbn + a_base[1]) ^ kxn);
            }
            mma16816(acc[0][4], a_cur[0], b0);
            mma16816(acc[0][5], a_cur[0], b0 + 2);
            mma16816(acc[1][4], a_cur[1], b0);
            mma16816(acc[1][5], a_cur[1], b0 + 2);
            // Refill the other stage after the first k16 step (barrier above
            // proved all warps finished consuming it).
            if (ksi == 0 && kt + 1 < NK) {
                load_stage(kt + 1, (kt + 1) & 1);
                asm volatile("cp.async.commit_group;\n");
            }
            mma16816(acc[0][6], a_cur[0], b1);
            mma16816(acc[0][7], a_cur[0], b1 + 2);
            mma16816(acc[1][6], a_cur[1], b1);
            mma16816(acc[1][7], a_cur[1], b1 + 2);
            if (ksi < 5) {
#pragma unroll
                for (int q = 0; q < 4; q++) {
                    a_cur[0][q] = a_nxt[0][q];
                    a_cur[1][q] = a_nxt[1][q];
                }
            }
            ks = ksn;
        }
    }

    // ---- Fused LSTM epilogue (two 64-row phases through smem) ----
    float* egs = (float*)smem;                      // [64][130] = 33280 B
    const float* c_s = (const float*)(smem + C_OFF);
#pragma unroll 1
    for (int half = 0; half < 2; half++) {
        __syncthreads();
        if ((wm >> 1) == half) {
            int rb = (wm & 1) * 32;
#pragma unroll
            for (int mi = 0; mi < 2; mi++)
#pragma unroll
                for (int ni = 0; ni < 8; ni++) {
                    int r = rb + mi * 16 + (lane >> 2);
                    int col = wn * 64 + ni * 8 + ((lane & 3) << 1);
                    egs[r * 130 + col]           = acc[mi][ni][0];
                    egs[r * 130 + col + 1]       = acc[mi][ni][1];
                    egs[(r + 8) * 130 + col]     = acc[mi][ni][2];
                    egs[(r + 8) * 130 + col + 1] = acc[mi][ni][3];
                }
        }
        __syncthreads();
#pragma unroll
        for (int i = 0; i < 8; i++) {
            int item = tid + i * 256;               // 2048 (row, hidden) items
            int ml = item >> 5, u = item & 31;
            float gi = egs[ml * 130 + 4 * u]     + bias_s[4 * u];
            float gf = egs[ml * 130 + 4 * u + 1] + bias_s[4 * u + 1];
            float go = egs[ml * 130 + 4 * u + 2] + bias_s[4 * u + 2];
            float gc = egs[ml * 130 + 4 * u + 3] + bias_s[4 * u + 3];
            float it = 1.f / (1.f + __expf(-gi));
            float ft = 1.f / (1.f + __expf(-gf));
            float ot = 1.f / (1.f + __expf(-go));
            float tc = 1.f - 2.f / (1.f + __expf(2.f * gc));   // tanh via MUFU
            int mg = mBase + half * 64 + ml;
            int ug = (nBase >> 2) + u;
            float cv = c_s[(half * 64 + ml) * 32 + u];
            float ct = ft * cv + it * tc;
            float ht = ot * (1.f - 2.f / (1.f + __expf(2.f * ct)));
            out[(size_t)mg * HH + ug] = ct;
            out[(size_t)BB * HH + (size_t)mg * HH + ug] = ht;
        }
    }
}

// ---------------------------------------------------------------------------
extern "C" void kernel_launch(void* const* d_in, const int* in_sizes, int n_in,
                              void* d_out, int out_size) {
    (void)in_sizes; (void)n_in; (void)out_size;
    const float* x  = (const float*)d_in[0];
    const float* h  = (const float*)d_in[1];
    const float* c  = (const float*)d_in[2];
    const float* Wx = (const float*)d_in[3];
    const float* bx = (const float*)d_in[4];
    const float* Wh = (const float*)d_in[5];
    const float* bh = (const float*)d_in[6];
    float* out = (float*)d_out;

    cudaFuncSetAttribute(lstm_gemm, cudaFuncAttributeMaxDynamicSharedMemorySize, SMEM_DYN);

    prep_all<<<NB_A + NB_W, 256>>>(x, h, Wx, bx, Wh, bh);
    lstm_gemm<<<dim3(NN / 128, BB / 128), 256, SMEM_DYN>>>(c, out);
}

// round 15
// speedup vs baseline: 1.1045x; 1.0545x over previous
#include <cuda_runtime.h>
#include <cuda_fp16.h>
#include <cstdint>

#define BB 32768
#define II 256
#define HH 512
#define KK 768        // I + H, single fp16 pass
#define NN 2048       // 4 * H gates

__device__ __half g_A[(size_t)BB * KK];   // [B][K]  fp16
__device__ __half g_W[(size_t)NN * KK];   // [N][K]  fp16, N interleaved (u,g)
__device__ float g_bias[NN];

// ---------------------------------------------------------------------------
// PTX helpers
// ---------------------------------------------------------------------------
__device__ __forceinline__ void cp_async16(uint32_t saddr, const void* gaddr) {
    asm volatile("cp.async.cg.shared.global [%0], [%1], 16;\n"
                 :: "r"(saddr), "l"(gaddr));
}
__device__ __forceinline__ void ldsm_x4(uint32_t* r, uint32_t addr) {
    asm volatile("ldmatrix.sync.aligned.m8n8.x4.shared.b16 {%0,%1,%2,%3}, [%4];\n"
                 : "=r"(r[0]), "=r"(r[1]), "=r"(r[2]), "=r"(r[3]) : "r"(addr));
}
__device__ __forceinline__ void mma16816(float* d, const uint32_t* a, const uint32_t* b) {
    asm volatile(
        "mma.sync.aligned.m16n8k16.row.col.f32.f16.f16.f32 "
        "{%0,%1,%2,%3}, {%4,%5,%6,%7}, {%8,%9}, {%0,%1,%2,%3};\n"
        : "+f"(d[0]), "+f"(d[1]), "+f"(d[2]), "+f"(d[3])
        : "r"(a[0]), "r"(a[1]), "r"(a[2]), "r"(a[3]), "r"(b[0]), "r"(b[1]));
}
__device__ __forceinline__ void stg_cs_v4(float* p, float a, float b, float c, float d) {
    asm volatile("st.global.cs.v4.f32 [%0], {%1, %2, %3, %4};\n"
                 :: "l"(p), "f"(a), "f"(b), "f"(c), "f"(d) : "memory");
}

// ---------------------------------------------------------------------------
// Merged prep kernel (fp16 A, W, bias). Gate cols interleaved:
// out col n <-> (u=n>>2, g=n&3); src row = g*H+u.
// ---------------------------------------------------------------------------
#define NB_A (BB * (KK / 4) / 256)     // 24576
#define NB_W (NN * (KK / 4) / 256)     // 1536

__global__ void prep_all(const float* __restrict__ x, const float* __restrict__ h,
                         const float* __restrict__ Wx, const float* __restrict__ bx,
                         const float* __restrict__ Wh, const float* __restrict__ bh) {
    int bidx = blockIdx.x;
    if (bidx < NB_A) {
        int idx = bidx * 256 + threadIdx.x;
        int b = idx / (KK / 4), kc = idx % (KK / 4);
        int k0 = kc * 4;
        float4 v;
        if (k0 < II) v = *(const float4*)(x + (size_t)b * II + k0);
        else         v = *(const float4*)(h + (size_t)b * HH + (k0 - II));
        union { __half h[4]; uint2 u2; } p;
        p.h[0] = __float2half_rn(v.x); p.h[1] = __float2half_rn(v.y);
        p.h[2] = __float2half_rn(v.z); p.h[3] = __float2half_rn(v.w);
        *(uint2*)(g_A + (size_t)b * KK + k0) = p.u2;
    } else {
        int idx = (bidx - NB_A) * 256 + threadIdx.x;
        int n = idx / (KK / 4), kc = idx % (KK / 4);
        int u = n >> 2, g = n & 3, src = g * HH + u;
        int k0 = kc * 4;
        float4 v;
        if (k0 < II) v = *(const float4*)(Wx + (size_t)src * II + k0);
        else         v = *(const float4*)(Wh + (size_t)src * HH + (k0 - II));
        union { __half h[4]; uint2 u2; } p;
        p.h[0] = __float2half_rn(v.x); p.h[1] = __float2half_rn(v.y);
        p.h[2] = __float2half_rn(v.z); p.h[3] = __float2half_rn(v.w);
        *(uint2*)(g_W + (size_t)n * KK + k0) = p.u2;
        if (kc == 0) g_bias[n] = bx[src] + bh[src];
    }
}

// ---------------------------------------------------------------------------
// Fused GEMM + LSTM epilogue (R12 structure; additive micro-opts only).
// CTA tile 128x128, K chunk 96, 2-stage ring, 8 warps 4x2, warp tile 32x64.
// Stage: 3 blocks of [128 rows x 64B]/operand, swizzle c ^= (row>>1)&3.
// Precomputed XOR-composable ldsm addresses; refill spread over steps 0-2;
// streaming epilogue stores. 2 CTAs/SM. c_in tile prefetched at start.
// ---------------------------------------------------------------------------
#define KCH 96
#define NK  (KK / KCH)        // 8
#define BLKB 8192             // one 128x64B block
#define TILEB (3 * BLKB)      // 24576 per operand per stage
#define STG  (2 * TILEB)      // 49152 per stage (A + B)
#define NSTAGE 2
#define C_OFF (NSTAGE * STG)  // 98304
#define SMEM_DYN (C_OFF + 16384)  // 114688

#define SWZ(row, c) ((((c) ^ (((row) >> 1) & 3)) << 4))

__global__ void __launch_bounds__(256, 2)
lstm_gemm(const float* __restrict__ c_in, float* __restrict__ out) {
    extern __shared__ __align__(16) unsigned char smem[];
    __shared__ float bias_s[128];

    const int tid  = threadIdx.x;
    const int warp = tid >> 5, lane = tid & 31;
    const int wm = warp >> 1, wn = warp & 1;       // 4x2 warp grid
    const int mBase = blockIdx.y * 128;
    const int nBase = blockIdx.x * 128;

    const uint32_t sbase = (uint32_t)__cvta_generic_to_shared(smem);
    if (tid < 128) bias_s[tid] = g_bias[nBase + tid];

    float acc[2][8][4];
#pragma unroll
    for (int mi = 0; mi < 2; mi++)
#pragma unroll
        for (int ni = 0; ni < 8; ni++)
#pragma unroll
            for (int d = 0; d < 4; d++) acc[mi][ni][d] = 0.f;

    const __half* gAp = g_A + (size_t)mBase * KK;
    const __half* gWp = g_W + (size_t)nBase * KK;

    // Precomputed ldsm base offsets; kk toggles bit 5 via XOR (carry-free:
    // disjoint bit fields), blk adds BLKB.
    uint32_t a_base[2], b_base[4];
#pragma unroll
    for (int mi = 0; mi < 2; mi++) {
        int row = wm * 32 + mi * 16 + (lane & 15);
        a_base[mi] = row * 64 + (((lane >> 4) ^ ((row >> 1) & 3)) << 4);
    }
#pragma unroll
    for (int p = 0; p < 4; p++) {
        int nrow = wn * 64 + p * 16 + ((lane >> 4) << 3) + (lane & 7);
        b_base[p] = TILEB + nrow * 64
                  + ((((lane >> 3) & 1) ^ ((nrow >> 1) & 3)) << 4);
    }

    // 3072 16B-chunks per stage, split into 3 parts of 4 j-blocks each
    // (part 0: A, part 1: A+B, part 2: B), 4 cp.async/thread per part.
    auto load_part = [&](int kt, int stage, int part) {
        uint32_t so = sbase + stage * STG;
#pragma unroll
        for (int jj = 0; jj < 4; jj++) {
            int j = part * 4 + jj;
            int idx = tid + j * 256;
            int isB = (j >= 6);
            int rem = idx - isB * 1536;
            int blk = rem >> 9;
            int row = (rem >> 2) & 127;
            int c   = rem & 3;
            const __half* src = (isB ? gWp : gAp)
                              + (size_t)row * KK + kt * KCH + blk * 32 + c * 8;
            cp_async16(so + isB * TILEB + blk * BLKB + row * 64 + SWZ(row, c), src);
        }
    };

    // Prefetch c_in tile: 128 rows x 32 f32 = 16KB (1024 chunks, 4/thread).
#pragma unroll
    for (int j = 0; j < 4; j++) {
        int idx = tid + j * 256;
        int row = idx >> 3, ch = idx & 7;
        cp_async16(sbase + C_OFF + row * 128 + ch * 16,
                   c_in + (size_t)(mBase + row) * HH + (nBase >> 2) + ch * 4);
    }
    load_part(0, 0, 0); load_part(0, 0, 1); load_part(0, 0, 2);
    asm volatile("cp.async.commit_group;\n");

    const int koff = warp & 3;     // stagger k16-step start across SMSP warps

    for (int kt = 0; kt < NK; kt++) {
        asm volatile("cp.async.wait_group 0;\n");
        __syncthreads();           // all warps done with the other stage

        const uint32_t so = sbase + (kt & 1) * STG;
        const int refill = (kt + 1 < NK);
#pragma unroll
        for (int ksi = 0; ksi < 6; ksi++) {        // six k16 steps per chunk
            int ks = ksi + koff; if (ks >= 6) ks -= 6;
            const uint32_t sb = so + (ks >> 1) * BLKB;
            const uint32_t kx = (uint32_t)(ks & 1) << 5;
            uint32_t a_regs[2][4];
            ldsm_x4(a_regs[0], (sb + a_base[0]) ^ kx);
            ldsm_x4(a_regs[1], (sb + a_base[1]) ^ kx);
            uint32_t b_regs[8][2];
#pragma unroll
            for (int p = 0; p < 4; p++) {          // each x4 covers two n-tiles
                uint32_t r[4];
                ldsm_x4(r, (sb + b_base[p]) ^ kx);
                b_regs[2 * p][0] = r[0]; b_regs[2 * p][1] = r[1];
                b_regs[2 * p + 1][0] = r[2]; b_regs[2 * p + 1][1] = r[3];
            }
#pragma unroll
            for (int mi = 0; mi < 2; mi++)
#pragma unroll
                for (int ni = 0; ni < 8; ni++)
                    mma16816(acc[mi][ni], a_regs[mi], b_regs[ni]);

            // Spread next-stage refill over steps 0-2 (4 cp.async/thread each);
            // commit at step 2 -> ~3 full steps of latency slack before the
            // next wait. Stage being filled was drained (barrier above).
            if (refill && ksi < 3) {
                load_part(kt + 1, (kt + 1) & 1, ksi);
                if (ksi == 2) asm volatile("cp.async.commit_group;\n");
            }
        }
    }

    // ---- Fused LSTM epilogue (two 64-row phases through smem) ----
    float* egs = (float*)smem;                      // [64][130] = 33280 B
    const float* c_s = (const float*)(smem + C_OFF);
#pragma unroll 1
    for (int half = 0; half < 2; half++) {
        __syncthreads();
        if ((wm >> 1) == half) {
            int rb = (wm & 1) * 32;
#pragma unroll
            for (int mi = 0; mi < 2; mi++)
#pragma unroll
                for (int ni = 0; ni < 8; ni++) {
                    int r = rb + mi * 16 + (lane >> 2);
                    int col = wn * 64 + ni * 8 + ((lane & 3) << 1);
                    egs[r * 130 + col]           = acc[mi][ni][0];
                    egs[r * 130 + col + 1]       = acc[mi][ni][1];
                    egs[(r + 8) * 130 + col]     = acc[mi][ni][2];
                    egs[(r + 8) * 130 + col + 1] = acc[mi][ni][3];
                }
        }
        __syncthreads();
#pragma unroll
        for (int i = 0; i < 8; i++) {
            int item = tid + i * 256;               // 2048 (row, hidden) items
            int ml = item >> 5, u = item & 31;
            float gi = egs[ml * 130 + 4 * u]     + bias_s[4 * u];
            float gf = egs[ml * 130 + 4 * u + 1] + bias_s[4 * u + 1];
            float go = egs[ml * 130 + 4 * u + 2] + bias_s[4 * u + 2];
            float gc = egs[ml * 130 + 4 * u + 3] + bias_s[4 * u + 3];
            float it = 1.f / (1.f + __expf(-gi));
            float ft = 1.f / (1.f + __expf(-gf));
            float ot = 1.f / (1.f + __expf(-go));
            float tc = 1.f - 2.f / (1.f + __expf(2.f * gc));   // tanh via MUFU
            int mg = mBase + half * 64 + ml;
            int ug = (nBase >> 2) + u;
            float cv = c_s[(half * 64 + ml) * 32 + u];
            float ct = ft * cv + it * tc;
            float ht = ot * (1.f - 2.f / (1.f + __expf(2.f * ct)));
            // Streaming stores: outputs are never re-read; keep A/W in L2.
            float* oc = out + (size_t)mg * HH + ug;
            asm volatile("st.global.cs.f32 [%0], %1;\n" :: "l"(oc), "f"(ct) : "memory");
            float* oh = out + (size_t)BB * HH + (size_t)mg * HH + ug;
            asm volatile("st.global.cs.f32 [%0], %1;\n" :: "l"(oh), "f"(ht) : "memory");
        }
    }
}

// ---------------------------------------------------------------------------
extern "C" void kernel_launch(void* const* d_in, const int* in_sizes, int n_in,
                              void* d_out, int out_size) {
    (void)in_sizes; (void)n_in; (void)out_size;
    const float* x  = (const float*)d_in[0];
    const float* h  = (const float*)d_in[1];
    const float* c  = (const float*)d_in[2];
    const float* Wx = (const float*)d_in[3];
    const float* bx = (const float*)d_in[4];
    const float* Wh = (const float*)d_in[5];
    const float* bh = (const float*)d_in[6];
    float* out = (float*)d_out;

    cudaFuncSetAttribute(lstm_gemm, cudaFuncAttributeMaxDynamicSharedMemorySize, SMEM_DYN);

    prep_all<<<NB_A + NB_W, 256>>>(x, h, Wx, bx, Wh, bh);
    lstm_gemm<<<dim3(NN / 128, BB / 128), 256, SMEM_DYN>>>(c, out);
}

// round 16
// speedup vs baseline: 1.1122x; 1.0069x over previous
#include <cuda_runtime.h>
#include <cuda_fp16.h>
#include <cstdint>

#define BB 32768
#define II 256
#define HH 512
#define KK 768        // I + H, single fp16 pass
#define NN 2048       // 4 * H gates

__device__ __half g_A[(size_t)BB * KK];   // [B][K]  fp16
__device__ __half g_W[(size_t)NN * KK];   // [N][K]  fp16, N interleaved (u,g)
__device__ float g_bias[NN];

// ---------------------------------------------------------------------------
// PTX helpers
// ---------------------------------------------------------------------------
__device__ __forceinline__ void cp_async16(uint32_t saddr, const void* gaddr) {
    asm volatile("cp.async.cg.shared.global [%0], [%1], 16;\n"
                 :: "r"(saddr), "l"(gaddr));
}
__device__ __forceinline__ void ldsm_x4(uint32_t* r, uint32_t addr) {
    asm volatile("ldmatrix.sync.aligned.m8n8.x4.shared.b16 {%0,%1,%2,%3}, [%4];\n"
                 : "=r"(r[0]), "=r"(r[1]), "=r"(r[2]), "=r"(r[3]) : "r"(addr));
}
__device__ __forceinline__ void mma16816(float* d, const uint32_t* a, const uint32_t* b) {
    asm volatile(
        "mma.sync.aligned.m16n8k16.row.col.f32.f16.f16.f32 "
        "{%0,%1,%2,%3}, {%4,%5,%6,%7}, {%8,%9}, {%0,%1,%2,%3};\n"
        : "+f"(d[0]), "+f"(d[1]), "+f"(d[2]), "+f"(d[3])
        : "r"(a[0]), "r"(a[1]), "r"(a[2]), "r"(a[3]), "r"(b[0]), "r"(b[1]));
}

// ---------------------------------------------------------------------------
// Merged prep kernel (fp16 A, W, bias). Gate cols interleaved:
// out col n <-> (u=n>>2, g=n&3); src row = g*H+u.
// ---------------------------------------------------------------------------
#define NB_A (BB * (KK / 4) / 256)     // 24576
#define NB_W (NN * (KK / 4) / 256)     // 1536

__global__ void prep_all(const float* __restrict__ x, const float* __restrict__ h,
                         const float* __restrict__ Wx, const float* __restrict__ bx,
                         const float* __restrict__ Wh, const float* __restrict__ bh) {
    int bidx = blockIdx.x;
    if (bidx < NB_A) {
        int idx = bidx * 256 + threadIdx.x;
        int b = idx / (KK / 4), kc = idx % (KK / 4);
        int k0 = kc * 4;
        float4 v;
        if (k0 < II) v = *(const float4*)(x + (size_t)b * II + k0);
        else         v = *(const float4*)(h + (size_t)b * HH + (k0 - II));
        union { __half h[4]; uint2 u2; } p;
        p.h[0] = __float2half_rn(v.x); p.h[1] = __float2half_rn(v.y);
        p.h[2] = __float2half_rn(v.z); p.h[3] = __float2half_rn(v.w);
        *(uint2*)(g_A + (size_t)b * KK + k0) = p.u2;
    } else {
        int idx = (bidx - NB_A) * 256 + threadIdx.x;
        int n = idx / (KK / 4), kc = idx % (KK / 4);
        int u = n >> 2, g = n & 3, src = g * HH + u;
        int k0 = kc * 4;
        float4 v;
        if (k0 < II) v = *(const float4*)(Wx + (size_t)src * II + k0);
        else         v = *(const float4*)(Wh + (size_t)src * HH + (k0 - II));
        union { __half h[4]; uint2 u2; } p;
        p.h[0] = __float2half_rn(v.x); p.h[1] = __float2half_rn(v.y);
        p.h[2] = __float2half_rn(v.z); p.h[3] = __float2half_rn(v.w);
        *(uint2*)(g_W + (size_t)n * KK + k0) = p.u2;
        if (kc == 0) g_bias[n] = bx[src] + bh[src];
    }
}

// ---------------------------------------------------------------------------
// Fused GEMM + LSTM epilogue.
// CTA tile 128x128, K chunk 96, 2-stage ring, 8 warps 4x2, warp tile 32x64.
// Stage: 3 blocks of [128 rows x 64B]/operand, swizzle c ^= (row>>1)&3.
// Step loop fully unrolled with COMPILE-TIME step indices (no stagger) so
// ptxas hoists ldsm addressing; refill spread over steps 0-2; streaming
// epilogue stores. 2 CTAs/SM. c_in tile prefetched at start.
// ---------------------------------------------------------------------------
#define KCH 96
#define NK  (KK / KCH)        // 8
#define BLKB 8192             // one 128x64B block
#define TILEB (3 * BLKB)      // 24576 per operand per stage
#define STG  (2 * TILEB)      // 49152 per stage (A + B)
#define NSTAGE 2
#define C_OFF (NSTAGE * STG)  // 98304
#define SMEM_DYN (C_OFF + 16384)  // 114688

#define SWZ(row, c) ((((c) ^ (((row) >> 1) & 3)) << 4))

__global__ void __launch_bounds__(256, 2)
lstm_gemm(const float* __restrict__ c_in, float* __restrict__ out) {
    extern __shared__ __align__(16) unsigned char smem[];
    __shared__ float bias_s[128];

    const int tid  = threadIdx.x;
    const int warp = tid >> 5, lane = tid & 31;
    const int wm = warp >> 1, wn = warp & 1;       // 4x2 warp grid
    const int mBase = blockIdx.y * 128;
    const int nBase = blockIdx.x * 128;

    const uint32_t sbase = (uint32_t)__cvta_generic_to_shared(smem);
    if (tid < 128) bias_s[tid] = g_bias[nBase + tid];

    float acc[2][8][4];
#pragma unroll
    for (int mi = 0; mi < 2; mi++)
#pragma unroll
        for (int ni = 0; ni < 8; ni++)
#pragma unroll
            for (int d = 0; d < 4; d++) acc[mi][ni][d] = 0.f;

    const __half* gAp = g_A + (size_t)mBase * KK;
    const __half* gWp = g_W + (size_t)nBase * KK;

    // Per-lane ldsm base offsets (step constants fold in at compile time).
    uint32_t a_base[2], b_base[4];
#pragma unroll
    for (int mi = 0; mi < 2; mi++) {
        int row = wm * 32 + mi * 16 + (lane & 15);
        a_base[mi] = row * 64 + (((lane >> 4) ^ ((row >> 1) & 3)) << 4);
    }
#pragma unroll
    for (int p = 0; p < 4; p++) {
        int nrow = wn * 64 + p * 16 + ((lane >> 4) << 3) + (lane & 7);
        b_base[p] = TILEB + nrow * 64
                  + ((((lane >> 3) & 1) ^ ((nrow >> 1) & 3)) << 4);
    }

    // 3072 16B-chunks per stage, split into 3 parts of 4 j-blocks each
    // (part 0: A, part 1: A+B, part 2: B), 4 cp.async/thread per part.
    auto load_part = [&](int kt, int stage, int part) {
        uint32_t so = sbase + stage * STG;
#pragma unroll
        for (int jj = 0; jj < 4; jj++) {
            int j = part * 4 + jj;
            int idx = tid + j * 256;
            int isB = (j >= 6);
            int rem = idx - isB * 1536;
            int blk = rem >> 9;
            int row = (rem >> 2) & 127;
            int c   = rem & 3;
            const __half* src = (isB ? gWp : gAp)
                              + (size_t)row * KK + kt * KCH + blk * 32 + c * 8;
            cp_async16(so + isB * TILEB + blk * BLKB + row * 64 + SWZ(row, c), src);
        }
    };

    // Prefetch c_in tile: 128 rows x 32 f32 = 16KB (1024 chunks, 4/thread).
#pragma unroll
    for (int j = 0; j < 4; j++) {
        int idx = tid + j * 256;
        int row = idx >> 3, ch = idx & 7;
        cp_async16(sbase + C_OFF + row * 128 + ch * 16,
                   c_in + (size_t)(mBase + row) * HH + (nBase >> 2) + ch * 4);
    }
    load_part(0, 0, 0); load_part(0, 0, 1); load_part(0, 0, 2);
    asm volatile("cp.async.commit_group;\n");

    for (int kt = 0; kt < NK; kt++) {
        asm volatile("cp.async.wait_group 0;\n");
        __syncthreads();           // all warps done with the other stage

        const uint32_t so = sbase + (kt & 1) * STG;
        const int refill = (kt + 1 < NK);
#pragma unroll
        for (int ksi = 0; ksi < 6; ksi++) {        // six k16 steps per chunk
            const uint32_t sb = so + (ksi >> 1) * BLKB;   // compile-time blk
            const uint32_t kx = (uint32_t)(ksi & 1) << 5; // compile-time kk
            uint32_t a_regs[2][4];
            ldsm_x4(a_regs[0], (sb + a_base[0]) ^ kx);
            ldsm_x4(a_regs[1], (sb + a_base[1]) ^ kx);
            uint32_t b_regs[8][2];
#pragma unroll
            for (int p = 0; p < 4; p++) {          // each x4 covers two n-tiles
                uint32_t r[4];
                ldsm_x4(r, (sb + b_base[p]) ^ kx);
                b_regs[2 * p][0] = r[0]; b_regs[2 * p][1] = r[1];
                b_regs[2 * p + 1][0] = r[2]; b_regs[2 * p + 1][1] = r[3];
            }
#pragma unroll
            for (int mi = 0; mi < 2; mi++)
#pragma unroll
                for (int ni = 0; ni < 8; ni++)
                    mma16816(acc[mi][ni], a_regs[mi], b_regs[ni]);

            // Spread next-stage refill over steps 0-2 (4 cp.async/thread each);
            // commit at step 2 -> ~3 full steps of latency slack before the
            // next wait. Stage being filled was drained (barrier above).
            if (refill && ksi < 3) {
                load_part(kt + 1, (kt + 1) & 1, ksi);
                if (ksi == 2) asm volatile("cp.async.commit_group;\n");
            }
        }
    }

    // ---- Fused LSTM epilogue (two 64-row phases through smem) ----
    float* egs = (float*)smem;                      // [64][130] = 33280 B
    const float* c_s = (const float*)(smem + C_OFF);
#pragma unroll 1
    for (int half = 0; half < 2; half++) {
        __syncthreads();
        if ((wm >> 1) == half) {
            int rb = (wm & 1) * 32;
#pragma unroll
            for (int mi = 0; mi < 2; mi++)
#pragma unroll
                for (int ni = 0; ni < 8; ni++) {
                    int r = rb + mi * 16 + (lane >> 2);
                    int col = wn * 64 + ni * 8 + ((lane & 3) << 1);
                    egs[r * 130 + col]           = acc[mi][ni][0];
                    egs[r * 130 + col + 1]       = acc[mi][ni][1];
                    egs[(r + 8) * 130 + col]     = acc[mi][ni][2];
                    egs[(r + 8) * 130 + col + 1] = acc[mi][ni][3];
                }
        }
        __syncthreads();
#pragma unroll
        for (int i = 0; i < 8; i++) {
            int item = tid + i * 256;               // 2048 (row, hidden) items
            int ml = item >> 5, u = item & 31;
            float gi = egs[ml * 130 + 4 * u]     + bias_s[4 * u];
            float gf = egs[ml * 130 + 4 * u + 1] + bias_s[4 * u + 1];
            float go = egs[ml * 130 + 4 * u + 2] + bias_s[4 * u + 2];
            float gc = egs[ml * 130 + 4 * u + 3] + bias_s[4 * u + 3];
            float it = 1.f / (1.f + __expf(-gi));
            float ft = 1.f / (1.f + __expf(-gf));
            float ot = 1.f / (1.f + __expf(-go));
            float tc = 1.f - 2.f / (1.f + __expf(2.f * gc));   // tanh via MUFU
            int mg = mBase + half * 64 + ml;
            int ug = (nBase >> 2) + u;
            float cv = c_s[(half * 64 + ml) * 32 + u];
            float ct = ft * cv + it * tc;
            float ht = ot * (1.f - 2.f / (1.f + __expf(2.f * ct)));
            // Streaming stores: outputs are never re-read; keep A/W in L2.
            float* oc = out + (size_t)mg * HH + ug;
            asm volatile("st.global.cs.f32 [%0], %1;\n" :: "l"(oc), "f"(ct) : "memory");
            float* oh = out + (size_t)BB * HH + (size_t)mg * HH + ug;
            asm volatile("st.global.cs.f32 [%0], %1;\n" :: "l"(oh), "f"(ht) : "memory");
        }
    }
}

// ---------------------------------------------------------------------------
extern "C" void kernel_launch(void* const* d_in, const int* in_sizes, int n_in,
                              void* d_out, int out_size) {
    (void)in_sizes; (void)n_in; (void)out_size;
    const float* x  = (const float*)d_in[0];
    const float* h  = (const float*)d_in[1];
    const float* c  = (const float*)d_in[2];
    const float* Wx = (const float*)d_in[3];
    const float* bx = (const float*)d_in[4];
    const float* Wh = (const float*)d_in[5];
    const float* bh = (const float*)d_in[6];
    float* out = (float*)d_out;

    cudaFuncSetAttribute(lstm_gemm, cudaFuncAttributeMaxDynamicSharedMemorySize, SMEM_DYN);

    prep_all<<<NB_A + NB_W, 256>>>(x, h, Wx, bx, Wh, bh);
    lstm_gemm<<<dim3(NN / 128, BB / 128), 256, SMEM_DYN>>>(c, out);
}

// round 17
// speedup vs baseline: 1.1352x; 1.0207x over previous
#include <cuda_runtime.h>
#include <cuda_fp16.h>
#include <cstdint>

#define BB 32768
#define II 256
#define HH 512
#define KK 768        // I + H, single fp16 pass
#define NN 2048       // 4 * H gates

__device__ __half g_A[(size_t)BB * KK];   // [B][K]  fp16
__device__ __half g_W[(size_t)NN * KK];   // [N][K]  fp16, N interleaved (u,g)
__device__ float g_bias[NN];

// ---------------------------------------------------------------------------
// PTX helpers
// ---------------------------------------------------------------------------
__device__ __forceinline__ void cp_async16(uint32_t saddr, const void* gaddr) {
    asm volatile("cp.async.cg.shared.global [%0], [%1], 16;\n"
                 :: "r"(saddr), "l"(gaddr));
}
__device__ __forceinline__ void ldsm_x4(uint32_t* r, uint32_t addr) {
    asm volatile("ldmatrix.sync.aligned.m8n8.x4.shared.b16 {%0,%1,%2,%3}, [%4];\n"
                 : "=r"(r[0]), "=r"(r[1]), "=r"(r[2]), "=r"(r[3]) : "r"(addr));
}
__device__ __forceinline__ void mma16816(float* d, const uint32_t* a, const uint32_t* b) {
    asm volatile(
        "mma.sync.aligned.m16n8k16.row.col.f32.f16.f16.f32 "
        "{%0,%1,%2,%3}, {%4,%5,%6,%7}, {%8,%9}, {%0,%1,%2,%3};\n"
        : "+f"(d[0]), "+f"(d[1]), "+f"(d[2]), "+f"(d[3])
        : "r"(a[0]), "r"(a[1]), "r"(a[2]), "r"(a[3]), "r"(b[0]), "r"(b[1]));
}

// ---------------------------------------------------------------------------
// Merged prep kernel (fp16 A, W, bias), 8 elems/thread.
// Gate cols interleaved: out col n <-> (u=n>>2, g=n&3); src row = g*H+u.
// 8 | 256 so a thread's 8-elem span never straddles the x/h boundary.
// ---------------------------------------------------------------------------
#define NB_A (BB * (KK / 8) / 256)     // 12288
#define NB_W (NN * (KK / 8) / 256)     // 768

__global__ void prep_all(const float* __restrict__ x, const float* __restrict__ h,
                         const float* __restrict__ Wx, const float* __restrict__ bx,
                         const float* __restrict__ Wh, const float* __restrict__ bh) {
    int bidx = blockIdx.x;
    if (bidx < NB_A) {
        int idx = bidx * 256 + threadIdx.x;
        int b = idx / (KK / 8), kc = idx % (KK / 8);
        int k0 = kc * 8;
        const float* src = (k0 < II) ? (x + (size_t)b * II + k0)
                                     : (h + (size_t)b * HH + (k0 - II));
        float4 v0 = *(const float4*)(src);
        float4 v1 = *(const float4*)(src + 4);
        union { __half h[8]; uint4 u4; } p;
        p.h[0] = __float2half_rn(v0.x); p.h[1] = __float2half_rn(v0.y);
        p.h[2] = __float2half_rn(v0.z); p.h[3] = __float2half_rn(v0.w);
        p.h[4] = __float2half_rn(v1.x); p.h[5] = __float2half_rn(v1.y);
        p.h[6] = __float2half_rn(v1.z); p.h[7] = __float2half_rn(v1.w);
        *(uint4*)(g_A + (size_t)b * KK + k0) = p.u4;
    } else {
        int idx = (bidx - NB_A) * 256 + threadIdx.x;
        int n = idx / (KK / 8), kc = idx % (KK / 8);
        int u = n >> 2, g = n & 3, src_row = g * HH + u;
        int k0 = kc * 8;
        const float* src = (k0 < II) ? (Wx + (size_t)src_row * II + k0)
                                     : (Wh + (size_t)src_row * HH + (k0 - II));
        float4 v0 = *(const float4*)(src);
        float4 v1 = *(const float4*)(src + 4);
        union { __half h[8]; uint4 u4; } p;
        p.h[0] = __float2half_rn(v0.x); p.h[1] = __float2half_rn(v0.y);
        p.h[2] = __float2half_rn(v0.z); p.h[3] = __float2half_rn(v0.w);
        p.h[4] = __float2half_rn(v1.x); p.h[5] = __float2half_rn(v1.y);
        p.h[6] = __float2half_rn(v1.z); p.h[7] = __float2half_rn(v1.w);
        *(uint4*)(g_W + (size_t)n * KK + k0) = p.u4;
        if (kc == 0) g_bias[n] = bx[src_row] + bh[src_row];
    }
}

// ---------------------------------------------------------------------------
// Fused GEMM + LSTM epilogue.
// CTA tile 128x128, K chunk 96, 2-stage ring, 8 warps 4x2, warp tile 32x64.
// Stage: 3 blocks of [128 rows x 64B]/operand, swizzle c ^= (row>>1)&3.
// Compile-time step indices; refill spread over steps 0-2; streaming stores.
// Bias folded into acc init (mma accumulates onto it). Single-phase epilogue.
// 2 CTAs/SM. c_in tile prefetched at start.
// ---------------------------------------------------------------------------
#define KCH 96
#define NK  (KK / KCH)        // 8
#define BLKB 8192             // one 128x64B block
#define TILEB (3 * BLKB)      // 24576 per operand per stage
#define STG  (2 * TILEB)      // 49152 per stage (A + B)
#define NSTAGE 2
#define C_OFF (NSTAGE * STG)  // 98304
#define SMEM_DYN (C_OFF + 16384)  // 114688

#define SWZ(row, c) ((((c) ^ (((row) >> 1) & 3)) << 4))

__global__ void __launch_bounds__(256, 2)
lstm_gemm(const float* __restrict__ c_in, float* __restrict__ out) {
    extern __shared__ __align__(16) unsigned char smem[];
    __shared__ float bias_s[128];

    const int tid  = threadIdx.x;
    const int warp = tid >> 5, lane = tid & 31;
    const int wm = warp >> 1, wn = warp & 1;       // 4x2 warp grid
    const int mBase = blockIdx.y * 128;
    const int nBase = blockIdx.x * 128;

    const uint32_t sbase = (uint32_t)__cvta_generic_to_shared(smem);
    if (tid < 128) bias_s[tid] = g_bias[nBase + tid];

    const __half* gAp = g_A + (size_t)mBase * KK;
    const __half* gWp = g_W + (size_t)nBase * KK;

    // Per-lane ldsm base offsets (step constants fold in at compile time).
    uint32_t a_base[2], b_base[4];
#pragma unroll
    for (int mi = 0; mi < 2; mi++) {
        int row = wm * 32 + mi * 16 + (lane & 15);
        a_base[mi] = row * 64 + (((lane >> 4) ^ ((row >> 1) & 3)) << 4);
    }
#pragma unroll
    for (int p = 0; p < 4; p++) {
        int nrow = wn * 64 + p * 16 + ((lane >> 4) << 3) + (lane & 7);
        b_base[p] = TILEB + nrow * 64
                  + ((((lane >> 3) & 1) ^ ((nrow >> 1) & 3)) << 4);
    }

    // 3072 16B-chunks per stage, split into 3 parts of 4 j-blocks each
    // (part 0: A, part 1: A+B, part 2: B), 4 cp.async/thread per part.
    auto load_part = [&](int kt, int stage, int part) {
        uint32_t so = sbase + stage * STG;
#pragma unroll
        for (int jj = 0; jj < 4; jj++) {
            int j = part * 4 + jj;
            int idx = tid + j * 256;
            int isB = (j >= 6);
            int rem = idx - isB * 1536;
            int blk = rem >> 9;
            int row = (rem >> 2) & 127;
            int c   = rem & 3;
            const __half* src = (isB ? gWp : gAp)
                              + (size_t)row * KK + kt * KCH + blk * 32 + c * 8;
            cp_async16(so + isB * TILEB + blk * BLKB + row * 64 + SWZ(row, c), src);
        }
    };

    // Prefetch c_in tile: 128 rows x 32 f32 = 16KB (1024 chunks, 4/thread).
#pragma unroll
    for (int j = 0; j < 4; j++) {
        int idx = tid + j * 256;
        int row = idx >> 3, ch = idx & 7;
        cp_async16(sbase + C_OFF + row * 128 + ch * 16,
                   c_in + (size_t)(mBase + row) * HH + (nBase >> 2) + ch * 4);
    }
    load_part(0, 0, 0); load_part(0, 0, 1); load_part(0, 0, 2);
    asm volatile("cp.async.commit_group;\n");

    // Bias visible to all threads, then fold it into the accumulator init:
    // gates = bias + A*W (mma accumulates onto init value).
    __syncthreads();
    float acc[2][8][4];
#pragma unroll
    for (int ni = 0; ni < 8; ni++) {
        int col = wn * 64 + ni * 8 + ((lane & 3) << 1);
        float b0 = bias_s[col], b1 = bias_s[col + 1];
#pragma unroll
        for (int mi = 0; mi < 2; mi++) {
            acc[mi][ni][0] = b0; acc[mi][ni][1] = b1;
            acc[mi][ni][2] = b0; acc[mi][ni][3] = b1;
        }
    }

    for (int kt = 0; kt < NK; kt++) {
        asm volatile("cp.async.wait_group 0;\n");
        __syncthreads();           // all warps done with the other stage

        const uint32_t so = sbase + (kt & 1) * STG;
        const int refill = (kt + 1 < NK);
#pragma unroll
        for (int ksi = 0; ksi < 6; ksi++) {        // six k16 steps per chunk
            const uint32_t sb = so + (ksi >> 1) * BLKB;   // compile-time blk
            const uint32_t kx = (uint32_t)(ksi & 1) << 5; // compile-time kk
            uint32_t a_regs[2][4];
            ldsm_x4(a_regs[0], (sb + a_base[0]) ^ kx);
            ldsm_x4(a_regs[1], (sb + a_base[1]) ^ kx);
            uint32_t b_regs[8][2];
#pragma unroll
            for (int p = 0; p < 4; p++) {          // each x4 covers two n-tiles
                uint32_t r[4];
                ldsm_x4(r, (sb + b_base[p]) ^ kx);
                b_regs[2 * p][0] = r[0]; b_regs[2 * p][1] = r[1];
                b_regs[2 * p + 1][0] = r[2]; b_regs[2 * p + 1][1] = r[3];
            }
#pragma unroll
            for (int mi = 0; mi < 2; mi++)
#pragma unroll
                for (int ni = 0; ni < 8; ni++)
                    mma16816(acc[mi][ni], a_regs[mi], b_regs[ni]);

            // Spread next-stage refill over steps 0-2 (4 cp.async/thread each);
            // commit at step 2 -> ~3 full steps of latency slack before the
            // next wait. Stage being filled was drained (barrier above).
            if (refill && ksi < 3) {
                load_part(kt + 1, (kt + 1) & 1, ksi);
                if (ksi == 2) asm volatile("cp.async.commit_group;\n");
            }
        }
    }

    // ---- Fused LSTM epilogue (single phase through smem) ----
    float* egs = (float*)smem;                      // [128][130] = 66560 B
    const float* c_s = (const float*)(smem + C_OFF);
    __syncthreads();                                // mainloop smem reads done
#pragma unroll
    for (int mi = 0; mi < 2; mi++)
#pragma unroll
        for (int ni = 0; ni < 8; ni++) {
            int r = wm * 32 + mi * 16 + (lane >> 2);
            int col = wn * 64 + ni * 8 + ((lane & 3) << 1);
            egs[r * 130 + col]           = acc[mi][ni][0];
            egs[r * 130 + col + 1]       = acc[mi][ni][1];
            egs[(r + 8) * 130 + col]     = acc[mi][ni][2];
            egs[(r + 8) * 130 + col + 1] = acc[mi][ni][3];
        }
    __syncthreads();
#pragma unroll
    for (int i = 0; i < 16; i++) {
        int item = tid + i * 256;                   // 4096 (row, hidden) items
        int ml = item >> 5, u = item & 31;
        float gi = egs[ml * 130 + 4 * u];
        float gf = egs[ml * 130 + 4 * u + 1];
        float go = egs[ml * 130 + 4 * u + 2];
        float gc = egs[ml * 130 + 4 * u + 3];
        float it = 1.f / (1.f + __expf(-gi));
        float ft = 1.f / (1.f + __expf(-gf));
        float ot = 1.f / (1.f + __expf(-go));
        float tc = 1.f - 2.f / (1.f + __expf(2.f * gc));   // tanh via MUFU
        int mg = mBase + ml;
        int ug = (nBase >> 2) + u;
        float cv = c_s[ml * 32 + u];
        float ct = ft * cv + it * tc;
        float ht = ot * (1.f - 2.f / (1.f + __expf(2.f * ct)));
        // Streaming stores: outputs are never re-read; keep A/W in L2.
        float* oc = out + (size_t)mg * HH + ug;
        asm volatile("st.global.cs.f32 [%0], %1;\n" :: "l"(oc), "f"(ct) : "memory");
        float* oh = out + (size_t)BB * HH + (size_t)mg * HH + ug;
        asm volatile("st.global.cs.f32 [%0], %1;\n" :: "l"(oh), "f"(ht) : "memory");
    }
}

// ---------------------------------------------------------------------------
extern "C" void kernel_launch(void* const* d_in, const int* in_sizes, int n_in,
                              void* d_out, int out_size) {
    (void)in_sizes; (void)n_in; (void)out_size;
    const float* x  = (const float*)d_in[0];
    const float* h  = (const float*)d_in[1];
    const float* c  = (const float*)d_in[2];
    const float* Wx = (const float*)d_in[3];
    const float* bx = (const float*)d_in[4];
    const float* Wh = (const float*)d_in[5];
    const float* bh = (const float*)d_in[6];
    float* out = (float*)d_out;

    cudaFuncSetAttribute(lstm_gemm, cudaFuncAttributeMaxDynamicSharedMemorySize, SMEM_DYN);

    prep_all<<<NB_A + NB_W, 256>>>(x, h, Wx, bx, Wh, bh);
    lstm_gemm<<<dim3(NN / 128, BB / 128), 256, SMEM_DYN>>>(c, out);
}